// round 4
// baseline (speedup 1.0000x reference)
#include <cuda_runtime.h>
#include <math.h>

// ----------------------------------------------------------------------------
// ModulatedDeformableConv2d (DCNv2-style) with residual offset output.
//   B=4, CIN=COUT=128, K=3, S=1, P=1, D=1, H=W=96, MASK_SCALE=2
// Outputs (concatenated in d_out, float32):
//   out    [4,128,96,96]  (4,718,592 floats)
//   offset [4, 18,96,96]  (  663,552 floats)
// ----------------------------------------------------------------------------

namespace {
constexpr int Bn    = 4;
constexpr int CIN_  = 128;
constexpr int COUT_ = 128;
constexpr int Hd    = 96;
constexpr int Wd    = 96;
constexpr int HW_   = Hd * Wd;          // 9216
constexpr int KKd   = CIN_ * 9;         // 1152 (= CIN * K*K)
constexpr int OUT_ELEMS = Bn * COUT_ * HW_;  // 4718592
}

// Scratch for the 27-channel offset/mask conv result (no cudaMalloc allowed).
__device__ float g_om[Bn * 27 * HW_];

// ----------------------------------------------------------------------------
// Kernel 1: om = conv3x3(x, w_offmask), 27 output channels, pad=1, no bias.
// GEMM formulation: [32(pad of 27) oc] x [1152 k] x [96 px (one row)].
// Writes all 27 channels to g_om; channels 0..17 also to the offset output.
// Grid: Bn*Hd blocks (one (b, h) row each), 256 threads.
// ----------------------------------------------------------------------------
__global__ __launch_bounds__(256) void offconv_kernel(
    const float* __restrict__ x,
    const float* __restrict__ wom,
    float* __restrict__ outp)
{
    __shared__ __align__(16) float As[32][36];   // [kk][oc], padded
    __shared__ float Bs[32][97];                 // [kk][px], padded

    const int bx = blockIdx.x;          // 0..383
    const int h  = bx % Hd;
    const int b  = bx / Hd;
    const int t  = threadIdx.x;
    const int ty = t >> 5;              // 0..7  -> oc group of 4
    const int tx = t & 31;              // 0..31 -> px group of 3

    float acc[4][3];
#pragma unroll
    for (int i = 0; i < 4; i++)
#pragma unroll
        for (int j = 0; j < 3; j++) acc[i][j] = 0.f;

    const float* xb = x + b * CIN_ * HW_;

    for (int kc = 0; kc < KKd; kc += 32) {
        // ---- fill As: w_offmask chunk [32 kk][32 oc] (oc>=27 zero-padded)
        {
            const int kk  = t & 31;
            const int ocb = t >> 5;
#pragma unroll
            for (int i = 0; i < 4; i++) {
                int oc = ocb + i * 8;
                As[kk][oc] = (oc < 27) ? __ldg(wom + oc * KKd + kc + kk) : 0.f;
            }
        }
        // ---- fill Bs: standard im2col chunk [32 kk][96 px], zero pad border
        for (int e = t; e < 32 * 96; e += 256) {
            const int kk   = e / 96;
            const int p    = e - kk * 96;
            const int kidx = kc + kk;
            const int c    = kidx / 9;
            const int k    = kidx - c * 9;
            const int ki   = k / 3;
            const int kj   = k - ki * 3;
            const int y    = h + ki - 1;
            const int xx   = p + kj - 1;
            float v = 0.f;
            if ((unsigned)y < (unsigned)Hd && (unsigned)xx < (unsigned)Wd)
                v = __ldg(xb + c * HW_ + y * Wd + xx);
            Bs[kk][p] = v;
        }
        __syncthreads();

#pragma unroll
        for (int kk = 0; kk < 32; kk++) {
            float4 a = *reinterpret_cast<const float4*>(&As[kk][ty * 4]);
            float av[4] = {a.x, a.y, a.z, a.w};
            float bv[3];
#pragma unroll
            for (int j = 0; j < 3; j++) bv[j] = Bs[kk][tx * 3 + j];
#pragma unroll
            for (int i = 0; i < 4; i++)
#pragma unroll
                for (int j = 0; j < 3; j++)
                    acc[i][j] = fmaf(av[i], bv[j], acc[i][j]);
        }
        __syncthreads();
    }

    // ---- epilogue: g_om (all 27 ch) + offset output (first 18 ch)
#pragma unroll
    for (int i = 0; i < 4; i++) {
        const int oc = ty * 4 + i;
        if (oc < 27) {
#pragma unroll
            for (int j = 0; j < 3; j++) {
                const int w = tx * 3 + j;
                const float v = acc[i][j];
                g_om[(b * 27 + oc) * HW_ + h * Wd + w] = v;
                if (oc < 18)
                    outp[OUT_ELEMS + (b * 18 + oc) * HW_ + h * Wd + w] = v;
            }
        }
    }
}

// ----------------------------------------------------------------------------
// Kernel 2: fused deformable im2col + GEMM.
// Block tile: 128 oc x 32 px (one b, one row h, 32 consecutive w).
// Per-block precompute: 9 taps x 32 px -> 4 clipped corner indices +
// 4 mask-folded bilinear corner weights (invalid corners -> weight 0,
// matching the reference's clip+validity semantics exactly).
// Mainloop: K=1152 in chunks of 32; 4x4 register micro-tile per thread.
// Grid: Bn*Hd*3 = 1152 blocks, 256 threads.
// ----------------------------------------------------------------------------
__global__ __launch_bounds__(256) void dcn_main_kernel(
    const float* __restrict__ x,
    const float* __restrict__ weight,
    const float* __restrict__ bias,
    float* __restrict__ outp)
{
    __shared__ __align__(16) float As[32][132];  // [kk][oc], padded, f4-aligned
    __shared__ __align__(16) float Bs[32][36];   // [kk][px], padded, f4-aligned
    __shared__ int4   sIdx[9 * 32];              // [tap][px] corner indices
    __shared__ float4 sWgt[9 * 32];              // [tap][px] corner weights
    __shared__ float  sBias[128];

    const int bx = blockIdx.x;                   // 0..1151
    const int wt = bx % 3;
    const int h  = (bx / 3) % Hd;
    const int b  = bx / (3 * Hd);
    const int w0 = wt * 32;
    const int t  = threadIdx.x;

    if (t < 128) sBias[t] = bias[t];

    // ---- precompute bilinear sampling metadata per (tap, pixel)
    for (int e = t; e < 288; e += 256) {
        const int k = e >> 5;                    // tap 0..8
        const int p = e & 31;                    // px in tile
        const int w = w0 + p;
        const float* om = g_om + (b * 27) * HW_ + h * Wd + w;
        const float o1 = om[k * HW_];            // y offset
        const float o2 = om[(9 + k) * HW_];      // x offset
        const float mr = om[(18 + k) * HW_];
        const float m  = 2.f / (1.f + expf(-mr));   // sigmoid * MASK_SCALE

        const int ki = k / 3, kj = k - ki * 3;
        const float py  = (float)(h - 1 + ki) + o1;
        const float pxf = (float)(w - 1 + kj) + o2;
        const float y0f = floorf(py), x0f = floorf(pxf);
        const float ly = py - y0f, lx = pxf - x0f;
        const int y0 = (int)y0f, x0 = (int)x0f;
        const int y1 = y0 + 1,  x1 = x0 + 1;

        const float v00 = ((unsigned)y0 < (unsigned)Hd && (unsigned)x0 < (unsigned)Wd) ? 1.f : 0.f;
        const float v01 = ((unsigned)y0 < (unsigned)Hd && (unsigned)x1 < (unsigned)Wd) ? 1.f : 0.f;
        const float v10 = ((unsigned)y1 < (unsigned)Hd && (unsigned)x0 < (unsigned)Wd) ? 1.f : 0.f;
        const float v11 = ((unsigned)y1 < (unsigned)Hd && (unsigned)x1 < (unsigned)Wd) ? 1.f : 0.f;

        const int y0c = min(max(y0, 0), Hd - 1), y1c = min(max(y1, 0), Hd - 1);
        const int x0c = min(max(x0, 0), Wd - 1), x1c = min(max(x1, 0), Wd - 1);

        sIdx[e] = make_int4(y0c * Wd + x0c, y0c * Wd + x1c,
                            y1c * Wd + x0c, y1c * Wd + x1c);
        const float hy = 1.f - ly, hx = 1.f - lx;
        sWgt[e] = make_float4(hy * hx * m * v00, hy * lx * m * v01,
                              ly * hx * m * v10, ly * lx * m * v11);
    }
    __syncthreads();

    float acc[4][4];
#pragma unroll
    for (int i = 0; i < 4; i++)
#pragma unroll
        for (int j = 0; j < 4; j++) acc[i][j] = 0.f;

    const int ty = t >> 3;   // 0..31 -> oc group of 4
    const int tx = t & 7;    // 0..7  -> px group of 4
    const float* xb = x + b * CIN_ * HW_;

    for (int kc = 0; kc < KKd; kc += 32) {
        // ---- fill As: weight chunk, vectorized float4 global loads
        {
            const int kkq = (t & 7) * 4;
            const int oc0 = t >> 3;
#pragma unroll
            for (int i = 0; i < 4; i++) {
                const int oc = oc0 + i * 32;
                float4 wv = *reinterpret_cast<const float4*>(weight + oc * KKd + kc + kkq);
                As[kkq + 0][oc] = wv.x;
                As[kkq + 1][oc] = wv.y;
                As[kkq + 2][oc] = wv.z;
                As[kkq + 3][oc] = wv.w;
            }
        }
        // ---- fill Bs: deformable-sampled columns (4 gathers per element)
        {
            const int p   = t & 31;
            const int kkb = t >> 5;
#pragma unroll
            for (int i = 0; i < 4; i++) {
                const int kk   = kkb + i * 8;
                const int kidx = kc + kk;
                const int c    = kidx / 9;
                const int k    = kidx - c * 9;
                const int e    = (k << 5) + p;
                const int4   id = sIdx[e];
                const float4 wv = sWgt[e];
                const float* xc = xb + c * HW_;
                float v = wv.x * __ldg(xc + id.x)
                        + wv.y * __ldg(xc + id.y)
                        + wv.z * __ldg(xc + id.z)
                        + wv.w * __ldg(xc + id.w);
                Bs[kk][p] = v;
            }
        }
        __syncthreads();

#pragma unroll
        for (int kk = 0; kk < 32; kk++) {
            float4 a  = *reinterpret_cast<const float4*>(&As[kk][ty * 4]);
            float4 bb = *reinterpret_cast<const float4*>(&Bs[kk][tx * 4]);
            float av[4] = {a.x, a.y, a.z, a.w};
            float bv[4] = {bb.x, bb.y, bb.z, bb.w};
#pragma unroll
            for (int i = 0; i < 4; i++)
#pragma unroll
                for (int j = 0; j < 4; j++)
                    acc[i][j] = fmaf(av[i], bv[j], acc[i][j]);
        }
        __syncthreads();
    }

    // ---- epilogue: bias + vectorized store
    const int w = w0 + tx * 4;
#pragma unroll
    for (int i = 0; i < 4; i++) {
        const int oc = ty * 4 + i;
        const float bb = sBias[oc];
        float4 r;
        r.x = acc[i][0] + bb;
        r.y = acc[i][1] + bb;
        r.z = acc[i][2] + bb;
        r.w = acc[i][3] + bb;
        *reinterpret_cast<float4*>(outp + (b * COUT_ + oc) * HW_ + h * Wd + w) = r;
    }
}

// ----------------------------------------------------------------------------
extern "C" void kernel_launch(void* const* d_in, const int* in_sizes, int n_in,
                              void* d_out, int out_size)
{
    const float* x    = (const float*)d_in[0];   // [4,128,96,96]
    const float* wgt  = (const float*)d_in[1];   // [128,128,3,3]
    const float* bias = (const float*)d_in[2];   // [128]
    const float* wom  = (const float*)d_in[3];   // [27,128,3,3]
    float* outp = (float*)d_out;

    offconv_kernel<<<Bn * Hd, 256>>>(x, wom, outp);          // 384 blocks
    dcn_main_kernel<<<Bn * Hd * 3, 256>>>(x, wgt, bias, outp); // 1152 blocks
}